// round 3
// baseline (speedup 1.0000x reference)
#include <cuda_runtime.h>
#include <math.h>

#define BT 256   // threads per block (main kernel)
#define M  8     // batch rows per block

using ull = unsigned long long;

// ---------------- problem constants ----------------
constexpr int Bsz = 1024, Tsz = 256, DIN = 128;
constexpr int NH0 = 269, NH1 = 179, NH2 = 64;
constexpr int CAT0 = DIN + NH0;   // 397
constexpr int CAT1 = NH0 + NH1;   // 448
constexpr int CAT2 = NH1 + NH2;   // 243
constexpr int CATP0 = 400, CATP1 = 448, CATP2 = 244;  // padded to mult of 4
constexpr int NO0 = 4 * NH0;      // 1076
constexpr int NO1 = 4 * NH1;      // 716
constexpr int NO2 = 4 * NH2;      // 256
constexpr int OUTD = 64;
constexpr long long PRED_ELEMS = (long long)Bsz * Tsz * OUTD;

// ---------------- device scratch ----------------
__device__ float g_WT0[CATP0 * NO0];
__device__ float g_WT1[CATP1 * NO1];
__device__ float g_WT2[CATP2 * NO2];
__device__ float g_bC0[NO0];
__device__ float g_bC1[NO1];
__device__ float g_bC2[NO2];
__device__ int   g_fmt[3];

// ---------------- f32x2 helpers ----------------
__device__ __forceinline__ ull pack2(float v) {
    ull r; asm("mov.b64 %0, {%1, %1};" : "=l"(r) : "f"(v)); return r;
}
__device__ __forceinline__ ull pack2(float a, float b) {
    ull r; asm("mov.b64 %0, {%1, %2};" : "=l"(r) : "f"(a), "f"(b)); return r;
}
__device__ __forceinline__ float2 unpack2(ull v) {
    float2 f; asm("mov.b64 {%0, %1}, %2;" : "=f"(f.x), "=f"(f.y) : "l"(v)); return f;
}
__device__ __forceinline__ void fma2(ull& d, ull a, ull b) {
    asm("fma.rn.f32x2 %0, %1, %2, %0;" : "+l"(d) : "l"(a), "l"(b));
}

// ---------------- mask dtype detection (unchanged, known-good) ----------------
__global__ void detect_kernel(const void* m0, int n0, const void* m1, int n1,
                              const void* m2, int n2) {
    const void* p = (blockIdx.x == 0) ? m0 : (blockIdx.x == 1) ? m1 : m2;
    int n = (blockIdx.x == 0) ? n0 : (blockIdx.x == 1) ? n1 : n2;
    __shared__ int fl;
    if (threadIdx.x == 0) fl = 0;
    __syncthreads();
    int nw = n >> 2;
    const unsigned* w = (const unsigned*)p;
    int loc = 0;
    for (int i = threadIdx.x; i < nw; i += blockDim.x) {
        unsigned v = w[i];
        if (v == 0x3F800000u) loc |= 1;
        else if (v == 0x3F803F80u || v == 0x00003F80u) loc |= 2;
        else if (v != 0u && v != 1u) loc |= 4;
    }
    atomicOr(&fl, loc);
    __syncthreads();
    if (threadIdx.x == 0) {
        int f = fl, fmt;
        if (f & 2) fmt = 3;
        else if (f & 1) fmt = 0;
        else if (f & 4) fmt = 2;
        else fmt = 1;
        g_fmt[blockIdx.x] = fmt;
    }
}

__device__ __forceinline__ bool maskbit(const void* p, int fmt, int idx) {
    switch (fmt) {
        case 0: return ((const float*)p)[idx] != 0.0f;
        case 1: return ((const int*)p)[idx] != 0;
        case 3: return ((const unsigned short*)p)[idx] != 0;
        default: return ((const unsigned char*)p)[idx] != 0;
    }
}

// ---------------- weight transpose + mask prep (unchanged, known-good) --------
__global__ void prep_kernel(const float* __restrict__ w1, const float* __restrict__ w2,
                            const float* __restrict__ wa, const float* __restrict__ wb,
                            const float* __restrict__ b1, const float* __restrict__ b2,
                            const float* __restrict__ ba, const float* __restrict__ bb,
                            const void* mask, int fmtIdx,
                            int CAT, int CATP, int NH,
                            float* __restrict__ WT, float* __restrict__ biasC) {
    int fmt = g_fmt[fmtIdx];
    int NO = 4 * NH;
    long long total = (long long)CATP * NO;
    for (long long idx = (long long)blockIdx.x * blockDim.x + threadIdx.x;
         idx < total; idx += (long long)gridDim.x * blockDim.x) {
        int k = (int)(idx / NO);
        int o = (int)(idx - (long long)k * NO);
        int g = o / NH;
        int j = o - g * NH;
        float v = 0.0f;
        if (k < CAT) {
            const float* ws = (g == 0) ? w1 : (g == 1) ? w2 : (g == 2) ? wa : wb;
            v = ws[j * CAT + k];
            if (g < 2) {
                if (!maskbit(mask, fmt, j * CAT + k)) v = 0.0f;
            }
        }
        WT[idx] = v;
        if (k == 0) {
            const float* bs = (g == 0) ? b1 : (g == 1) ? b2 : (g == 2) ? ba : bb;
            biasC[o] = bs[j];
        }
    }
}

// ---------------- main persistent kernel ----------------
// Activations stored TRANSPOSED: xt[k][r] so row-pairs are contiguous 8-byte
// units for f32x2 math. Gate pre-activations likewise Gt[o][r].
struct SM {
    float xt0[CATP0][M];
    float xt1[CATP1][M];
    float xt2[CATP2][M];
    float Gt[NO0][M];
    float fcT[OUTD * OUTD];
    float fcb[OUTD];
    float b0[NO0];
    float b1[NO1];
    float b2[NO2];
};

// 4 outputs x 8 rows per thread (rows packed in f32x2 pairs)
template <int CATP, int NOUT>
__device__ __forceinline__ void gemm8(const float* __restrict__ WT,
                                      const float* __restrict__ bs,
                                      const float (*__restrict__ XT)[M],
                                      float (*__restrict__ GT)[M], int quad) {
    const int o0 = quad * 4;
    ull acc[4][4];
#pragma unroll
    for (int o = 0; o < 4; ++o) {
        ull bb = pack2(bs[o0 + o]);
        acc[o][0] = bb; acc[o][1] = bb; acc[o][2] = bb; acc[o][3] = bb;
    }
    const float* wp = WT + o0;
#pragma unroll 4
    for (int k = 0; k < CATP; ++k) {
        float4 w = __ldg((const float4*)(wp + (size_t)k * NOUT));
        ull wd0 = pack2(w.x), wd1 = pack2(w.y), wd2 = pack2(w.z), wd3 = pack2(w.w);
        ulonglong2 xa = *(const ulonglong2*)&XT[k][0];
        ulonglong2 xb = *(const ulonglong2*)&XT[k][4];
        fma2(acc[0][0], wd0, xa.x); fma2(acc[0][1], wd0, xa.y);
        fma2(acc[0][2], wd0, xb.x); fma2(acc[0][3], wd0, xb.y);
        fma2(acc[1][0], wd1, xa.x); fma2(acc[1][1], wd1, xa.y);
        fma2(acc[1][2], wd1, xb.x); fma2(acc[1][3], wd1, xb.y);
        fma2(acc[2][0], wd2, xa.x); fma2(acc[2][1], wd2, xa.y);
        fma2(acc[2][2], wd2, xb.x); fma2(acc[2][3], wd2, xb.y);
        fma2(acc[3][0], wd3, xa.x); fma2(acc[3][1], wd3, xa.y);
        fma2(acc[3][2], wd3, xb.x); fma2(acc[3][3], wd3, xb.y);
    }
#pragma unroll
    for (int o = 0; o < 4; ++o)
#pragma unroll
        for (int p = 0; p < 4; ++p)
            *(ull*)&GT[o0 + o][2 * p] = acc[o][p];
}

// 4 outputs x 4 rows per thread (half = which 4-row group)
template <int CATP, int NOUT>
__device__ __forceinline__ void gemm4(const float* __restrict__ WT,
                                      const float* __restrict__ bs,
                                      const float (*__restrict__ XT)[M],
                                      float (*__restrict__ GT)[M], int quad, int half) {
    const int o0 = quad * 4;
    const int rb = half * 4;
    ull acc[4][2];
#pragma unroll
    for (int o = 0; o < 4; ++o) {
        ull bb = pack2(bs[o0 + o]);
        acc[o][0] = bb; acc[o][1] = bb;
    }
    const float* wp = WT + o0;
#pragma unroll 4
    for (int k = 0; k < CATP; ++k) {
        float4 w = __ldg((const float4*)(wp + (size_t)k * NOUT));
        ull wd0 = pack2(w.x), wd1 = pack2(w.y), wd2 = pack2(w.z), wd3 = pack2(w.w);
        ulonglong2 xa = *(const ulonglong2*)&XT[k][rb];
        fma2(acc[0][0], wd0, xa.x); fma2(acc[0][1], wd0, xa.y);
        fma2(acc[1][0], wd1, xa.x); fma2(acc[1][1], wd1, xa.y);
        fma2(acc[2][0], wd2, xa.x); fma2(acc[2][1], wd2, xa.y);
        fma2(acc[3][0], wd3, xa.x); fma2(acc[3][1], wd3, xa.y);
    }
#pragma unroll
    for (int o = 0; o < 4; ++o) {
        *(ull*)&GT[o0 + o][rb]     = acc[o][0];
        *(ull*)&GT[o0 + o][rb + 2] = acc[o][1];
    }
}

// 4 outputs x 2 rows per thread (rp = row-pair index)
template <int CATP, int NOUT>
__device__ __forceinline__ void gemm2(const float* __restrict__ WT,
                                      const float* __restrict__ bs,
                                      const float (*__restrict__ XT)[M],
                                      float (*__restrict__ GT)[M], int quad, int rp) {
    const int o0 = quad * 4;
    ull acc[4];
#pragma unroll
    for (int o = 0; o < 4; ++o) acc[o] = pack2(bs[o0 + o]);
    const float* wp = WT + o0;
#pragma unroll 4
    for (int k = 0; k < CATP; ++k) {
        float4 w = __ldg((const float4*)(wp + (size_t)k * NOUT));
        ull wd0 = pack2(w.x), wd1 = pack2(w.y), wd2 = pack2(w.z), wd3 = pack2(w.w);
        ull x2 = *(const ull*)&XT[k][2 * rp];
        fma2(acc[0], wd0, x2); fma2(acc[1], wd1, x2);
        fma2(acc[2], wd2, x2); fma2(acc[3], wd3, x2);
    }
#pragma unroll
    for (int o = 0; o < 4; ++o) *(ull*)&GT[o0 + o][2 * rp] = acc[o];
}

// 4 outputs x 1 row per thread: outputs packed in f32x2 (weights naturally
// contiguous), x duplicated. Used for the layer-0 tail quads.
template <int CATP, int NOUT>
__device__ __forceinline__ void gemm1(const float* __restrict__ WT,
                                      const float* __restrict__ bs,
                                      const float (*__restrict__ XT)[M],
                                      float (*__restrict__ GT)[M], int quad, int r) {
    const int o0 = quad * 4;
    ull a01 = pack2(bs[o0], bs[o0 + 1]);
    ull a23 = pack2(bs[o0 + 2], bs[o0 + 3]);
    const float* wp = WT + o0;
#pragma unroll 4
    for (int k = 0; k < CATP; ++k) {
        ulonglong2 w2 = __ldg((const ulonglong2*)(wp + (size_t)k * NOUT));
        ull xd = pack2(XT[k][r]);
        fma2(a01, w2.x, xd);
        fma2(a23, w2.y, xd);
    }
    float2 f01 = unpack2(a01), f23 = unpack2(a23);
    GT[o0][r] = f01.x; GT[o0 + 1][r] = f01.y;
    GT[o0 + 2][r] = f23.x; GT[o0 + 3][r] = f23.y;
}

__device__ __forceinline__ float cfc_cell(float f1, float f2, float ga, float gb) {
    float s = 1.0f / (1.0f + __expf(-(ga + gb)));
    return tanhf(f1) * (1.0f - s) + s * tanhf(f2);
}

// combine in transposed layout: thread j processes all 8 rows (vector ld/st)
template <int NH, bool DUAL>
__device__ __forceinline__ void combineT(const float (*__restrict__ GT)[M],
                                         float (*__restrict__ A)[M], int oA,
                                         float (*__restrict__ Bv)[M], int oB) {
    for (int j = threadIdx.x; j < NH; j += BT) {
        float4 f1a = *(const float4*)&GT[j][0];
        float4 f1b = *(const float4*)&GT[j][4];
        float4 f2a = *(const float4*)&GT[NH + j][0];
        float4 f2b = *(const float4*)&GT[NH + j][4];
        float4 gaa = *(const float4*)&GT[2 * NH + j][0];
        float4 gab = *(const float4*)&GT[2 * NH + j][4];
        float4 gba = *(const float4*)&GT[3 * NH + j][0];
        float4 gbb = *(const float4*)&GT[3 * NH + j][4];
        float4 na, nb;
        na.x = cfc_cell(f1a.x, f2a.x, gaa.x, gba.x);
        na.y = cfc_cell(f1a.y, f2a.y, gaa.y, gba.y);
        na.z = cfc_cell(f1a.z, f2a.z, gaa.z, gba.z);
        na.w = cfc_cell(f1a.w, f2a.w, gaa.w, gba.w);
        nb.x = cfc_cell(f1b.x, f2b.x, gab.x, gbb.x);
        nb.y = cfc_cell(f1b.y, f2b.y, gab.y, gbb.y);
        nb.z = cfc_cell(f1b.z, f2b.z, gab.z, gbb.z);
        nb.w = cfc_cell(f1b.w, f2b.w, gab.w, gbb.w);
        *(float4*)&A[oA + j][0] = na;
        *(float4*)&A[oA + j][4] = nb;
        if (DUAL) {
            *(float4*)&Bv[oB + j][0] = na;
            *(float4*)&Bv[oB + j][4] = nb;
        }
    }
}

__global__ __launch_bounds__(BT, 1)
void ncp_main(const float* __restrict__ x, const float* __restrict__ hidden,
              const float* __restrict__ fc_w, const float* __restrict__ fc_b,
              float* __restrict__ out) {
    extern __shared__ char smem_raw[];
    SM* sm = (SM*)smem_raw;
    const int tid = threadIdx.x;
    const int lane = tid & 31;
    const int wid = tid >> 5;
    const int row0 = blockIdx.x * M;

    // ---- init ----
    for (int i = tid; i < NO0; i += BT) sm->b0[i] = g_bC0[i];
    for (int i = tid; i < NO1; i += BT) sm->b1[i] = g_bC1[i];
    for (int i = tid; i < NO2; i += BT) sm->b2[i] = g_bC2[i];
    for (int i = tid; i < OUTD * OUTD; i += BT) {
        int mm = i >> 6, o = i & 63;
        sm->fcT[i] = __ldg(&fc_w[o * OUTD + mm]);
    }
    if (tid < OUTD) sm->fcb[tid] = fc_b[tid];
    for (int i = tid; i < M * 512; i += BT) {
        int r = i >> 9, c = i & 511;
        float v = hidden[(long long)(row0 + r) * 512 + c];
        if (c < NH0)              sm->xt0[DIN + c][r] = v;
        else if (c < NH0 + NH1)   sm->xt1[c][r] = v;
        else                      sm->xt2[NH1 + (c - NH0 - NH1)][r] = v;
    }
    if (tid < M) {
        sm->xt0[397][tid] = 0.0f; sm->xt0[398][tid] = 0.0f; sm->xt0[399][tid] = 0.0f;
        sm->xt2[243][tid] = 0.0f;
    }
    __syncthreads();

    // ---- sequential timestep loop ----
    for (int t = 0; t < Tsz; ++t) {
        // load x_t transposed: r = tid&7, col base = tid>>3 (conflict-free STS)
        {
            int r = tid & 7, cb = tid >> 3;
            const float* xp = x + ((long long)(row0 + r) * Tsz + t) * DIN;
#pragma unroll
            for (int u = 0; u < 4; ++u)
                sm->xt0[cb + 32 * u][r] = __ldg(&xp[cb + 32 * u]);
        }
        __syncthreads();

        // --- layer 0: 269 quads = 256 (all threads) + 13-quad tail as 104
        //     single-row units on warps 0..3 (one tail loop per SMSP) ---
        gemm8<CATP0, NO0>(g_WT0, sm->b0, sm->xt0, sm->Gt, tid);
        if (wid < 4 && lane < 26) {
            int idx = wid * 26 + lane;                 // 0..103
            gemm1<CATP0, NO0>(g_WT0, sm->b0, sm->xt0, sm->Gt,
                              256 + (idx >> 3), idx & 7);
        }
        __syncthreads();
        combineT<NH0, true>(sm->Gt, sm->xt1, 0, sm->xt0, DIN);
        __syncthreads();

        // --- layer 1: 179 quads x 2 halves = 358 4-row units:
        //     256 on all threads + 102 on warps 0..3 ---
        gemm4<CATP1, NO1>(g_WT1, sm->b1, sm->xt1, sm->Gt, tid >> 1, tid & 1);
        if (wid < 4) {
            int u = 256 + wid * 32 + lane;
            if (u < 358)
                gemm4<CATP1, NO1>(g_WT1, sm->b1, sm->xt1, sm->Gt, u >> 1, u & 1);
        }
        __syncthreads();
        combineT<NH1, true>(sm->Gt, sm->xt2, 0, sm->xt1, NH0);
        __syncthreads();

        // --- layer 2: 64 quads x 4 row-pairs = 256 units, all threads ---
        gemm2<CATP2, NO2>(g_WT2, sm->b2, sm->xt2, sm->Gt, tid >> 2, tid & 3);
        __syncthreads();
        combineT<NH2, false>(sm->Gt, sm->xt2, NH1, sm->xt2, NH1);
        __syncthreads();

        // --- fused output projection ---
        for (int idx = tid; idx < M * OUTD; idx += BT) {
            int r = idx >> 6, o = idx & 63;
            float a = sm->fcb[o];
#pragma unroll 8
            for (int mm = 0; mm < OUTD; ++mm)
                a += sm->fcT[mm * OUTD + o] * sm->xt2[NH1 + mm][r];
            out[((long long)(row0 + r) * Tsz + t) * OUTD + o] = a;
        }
        // no trailing sync needed: next iteration's x-load writes xt0 rows <128
        // only, and a barrier precedes the next gemm.
    }
    __syncthreads();

    // ---- final hidden state ----
    float* hn = out + PRED_ELEMS;
    for (int i = tid; i < M * 512; i += BT) {
        int r = i >> 9, c = i & 511;
        float v;
        if (c < NH0)            v = sm->xt0[DIN + c][r];
        else if (c < NH0 + NH1) v = sm->xt1[c][r];
        else                    v = sm->xt2[NH1 + (c - NH0 - NH1)][r];
        hn[(long long)(row0 + r) * 512 + c] = v;
    }
}

// ---------------- host launcher ----------------
extern "C" void kernel_launch(void* const* d_in, const int* in_sizes, int n_in,
                              void* d_out, int out_size) {
    (void)n_in; (void)out_size;
    const float* x      = (const float*)d_in[0];
    const float* hidden = (const float*)d_in[1];
    const void*  m0     = d_in[2];
    const void*  m1     = d_in[3];
    const void*  m2     = d_in[4];
    const float* ff1_w0 = (const float*)d_in[5];
    const float* ff1_b0 = (const float*)d_in[6];
    const float* ff2_w0 = (const float*)d_in[7];
    const float* ff2_b0 = (const float*)d_in[8];
    const float* ta_w0  = (const float*)d_in[9];
    const float* ta_b0  = (const float*)d_in[10];
    const float* tb_w0  = (const float*)d_in[11];
    const float* tb_b0  = (const float*)d_in[12];
    const float* ff1_w1 = (const float*)d_in[13];
    const float* ff1_b1 = (const float*)d_in[14];
    const float* ff2_w1 = (const float*)d_in[15];
    const float* ff2_b1 = (const float*)d_in[16];
    const float* ta_w1  = (const float*)d_in[17];
    const float* ta_b1  = (const float*)d_in[18];
    const float* tb_w1  = (const float*)d_in[19];
    const float* tb_b1  = (const float*)d_in[20];
    const float* ff1_w2 = (const float*)d_in[21];
    const float* ff1_b2 = (const float*)d_in[22];
    const float* ff2_w2 = (const float*)d_in[23];
    const float* ff2_b2 = (const float*)d_in[24];
    const float* ta_w2  = (const float*)d_in[25];
    const float* ta_b2  = (const float*)d_in[26];
    const float* tb_w2  = (const float*)d_in[27];
    const float* tb_b2  = (const float*)d_in[28];
    const float* fc_w   = (const float*)d_in[29];
    const float* fc_b   = (const float*)d_in[30];
    float* out = (float*)d_out;

    float *wt0, *wt1, *wt2, *bc0, *bc1, *bc2;
    cudaGetSymbolAddress((void**)&wt0, g_WT0);
    cudaGetSymbolAddress((void**)&wt1, g_WT1);
    cudaGetSymbolAddress((void**)&wt2, g_WT2);
    cudaGetSymbolAddress((void**)&bc0, g_bC0);
    cudaGetSymbolAddress((void**)&bc1, g_bC1);
    cudaGetSymbolAddress((void**)&bc2, g_bC2);

    detect_kernel<<<3, 256>>>(m0, in_sizes[2], m1, in_sizes[3], m2, in_sizes[4]);

    int blocks0 = (CATP0 * NO0 + 255) / 256;
    int blocks1 = (CATP1 * NO1 + 255) / 256;
    int blocks2 = (CATP2 * NO2 + 255) / 256;
    prep_kernel<<<blocks0, 256>>>(ff1_w0, ff2_w0, ta_w0, tb_w0,
                                  ff1_b0, ff2_b0, ta_b0, tb_b0,
                                  m0, 0, CAT0, CATP0, NH0, wt0, bc0);
    prep_kernel<<<blocks1, 256>>>(ff1_w1, ff2_w1, ta_w1, tb_w1,
                                  ff1_b1, ff2_b1, ta_b1, tb_b1,
                                  m1, 1, CAT1, CATP1, NH1, wt1, bc1);
    prep_kernel<<<blocks2, 256>>>(ff1_w2, ff2_w2, ta_w2, tb_w2,
                                  ff1_b2, ff2_b2, ta_b2, tb_b2,
                                  m2, 2, CAT2, CATP2, NH2, wt2, bc2);

    cudaFuncSetAttribute(ncp_main, cudaFuncAttributeMaxDynamicSharedMemorySize,
                         (int)sizeof(SM));
    ncp_main<<<Bsz / M, BT, sizeof(SM)>>>(x, hidden, fc_w, fc_b, out);
}

// round 7
// speedup vs baseline: 1.5589x; 1.5589x over previous
#include <cuda_runtime.h>
#include <math.h>

#define BT 256   // threads per block (main kernel)
#define M  8     // batch rows per block

// ---------------- problem constants ----------------
constexpr int Bsz = 1024, Tsz = 256, DIN = 128;
constexpr int NH0 = 269, NH1 = 179, NH2 = 64;
constexpr int CAT0 = DIN + NH0;   // 397
constexpr int CAT1 = NH0 + NH1;   // 448
constexpr int CAT2 = NH1 + NH2;   // 243
constexpr int CATP0 = 400, CATP1 = 448, CATP2 = 244;  // padded k
constexpr int OUTD = 64;
constexpr long long PRED_ELEMS = (long long)Bsz * Tsz * OUTD;

// gate strides in the per-gate weight arrays
constexpr int GS0 = CATP0 * NH0;   // 107600
constexpr int GS1 = CATP1 * NH1;   // 80192
constexpr int GS2 = CATP2 * NH2;   // 15616

// ---------------- device scratch ----------------
__device__ float g_W0[3 * GS0];   // [gate][k][j], gates: ff1, ff2, ta+tb
__device__ float g_W1[3 * GS1];
__device__ float g_W2[3 * GS2];
__device__ float g_B0[3 * NH0];
__device__ float g_B1[3 * NH1];
__device__ float g_B2[3 * NH2];
__device__ int   g_fmt[3];

// ---------------- mask dtype detection (unchanged, known-good) ----------------
__global__ void detect_kernel(const void* m0, int n0, const void* m1, int n1,
                              const void* m2, int n2) {
    const void* p = (blockIdx.x == 0) ? m0 : (blockIdx.x == 1) ? m1 : m2;
    int n = (blockIdx.x == 0) ? n0 : (blockIdx.x == 1) ? n1 : n2;
    __shared__ int fl;
    if (threadIdx.x == 0) fl = 0;
    __syncthreads();
    int nw = n >> 2;
    const unsigned* w = (const unsigned*)p;
    int loc = 0;
    for (int i = threadIdx.x; i < nw; i += blockDim.x) {
        unsigned v = w[i];
        if (v == 0x3F800000u) loc |= 1;
        else if (v == 0x3F803F80u || v == 0x00003F80u) loc |= 2;
        else if (v != 0u && v != 1u) loc |= 4;
    }
    atomicOr(&fl, loc);
    __syncthreads();
    if (threadIdx.x == 0) {
        int f = fl, fmt;
        if (f & 2) fmt = 3;
        else if (f & 1) fmt = 0;
        else if (f & 4) fmt = 2;
        else fmt = 1;
        g_fmt[blockIdx.x] = fmt;
    }
}

__device__ __forceinline__ bool maskbit(const void* p, int fmt, int idx) {
    switch (fmt) {
        case 0: return ((const float*)p)[idx] != 0.0f;
        case 1: return ((const int*)p)[idx] != 0;
        case 3: return ((const unsigned short*)p)[idx] != 0;
        default: return ((const unsigned char*)p)[idx] != 0;
    }
}

// ---------------- weight prep: per-gate transpose, mask, ta+tb fold ----------
// dst W[g*GS + k*NH + j]; g=0 ff1 (masked), g=1 ff2 (masked), g=2 wa+wb.
// bias Bc[g*NH + j]; g=2 -> ba+bb. Pad rows k>=CAT are zeroed.
__global__ void prep3_kernel(const float* __restrict__ w1, const float* __restrict__ w2,
                             const float* __restrict__ wa, const float* __restrict__ wb,
                             const float* __restrict__ b1, const float* __restrict__ b2,
                             const float* __restrict__ ba, const float* __restrict__ bb,
                             const void* mask, int fmtIdx,
                             int CAT, int CATP, int NH,
                             float* __restrict__ W, float* __restrict__ Bc) {
    int fmt = g_fmt[fmtIdx];
    long long per = (long long)CATP * NH;
    long long total = 3 * per;
    for (long long idx = (long long)blockIdx.x * blockDim.x + threadIdx.x;
         idx < total; idx += (long long)gridDim.x * blockDim.x) {
        int g = (int)(idx / per);
        long long rem = idx - (long long)g * per;
        int k = (int)(rem / NH);
        int j = (int)(rem - (long long)k * NH);
        float v = 0.0f;
        if (k < CAT) {
            if (g == 2) {
                v = wa[j * CAT + k] + wb[j * CAT + k];
            } else {
                v = (g == 0) ? w1[j * CAT + k] : w2[j * CAT + k];
                if (!maskbit(mask, fmt, j * CAT + k)) v = 0.0f;
            }
        }
        W[idx] = v;
        if (k == 0) {
            Bc[g * NH + j] = (g == 0) ? b1[j] : (g == 1) ? b2[j] : (ba[j] + bb[j]);
        }
    }
}

// ---------------- main persistent kernel ----------------
// Activations transposed: xt[k][r]. xt0 double-buffered (fused epilogue writes
// next-step h0 while other lanes still read current h0).
struct SM {
    float xt0[2][CATP0][M];        // [buf][ x(128) | h0(269) | pad(3) ]
    float xt1[CATP1][M];           // [ n0(269) | h1(179) ]
    float xt2[CATP2][M];           // [ n1(179) | h2(64) | pad(1) ]
    float P0[8][13][3][M];         // L0 tail partials [chunk][ju][gate][row]
    float P1[2][NH1][3][M];        // L1 partials [khalf][j][gate][row]
    float P2[4][NH2][3][M];        // L2 partials [kq][j][gate][row]
    float fcT[OUTD * OUTD];        // fcT[m*64+o] = fc_w[o][m]
    float fcb[OUTD];
    float b0[3 * NH0];
    float b1[3 * NH1];
    float b2[3 * NH2];
};

// 3-gate GEMM for one hidden unit j, 8 rows, k-range [k0, k0+KLEN).
template <int KLEN, int NH, int GS>
__device__ __forceinline__ void gemm3(const float* __restrict__ W, int j, int k0,
                                      const float (*__restrict__ xt)[M],
                                      float* __restrict__ a1,
                                      float* __restrict__ a2,
                                      float* __restrict__ a3) {
    const float* p = W + (size_t)k0 * NH + j;
#pragma unroll 4
    for (int k = 0; k < KLEN; ++k) {
        float w1 = __ldg(p);
        float w2 = __ldg(p + GS);
        float w3 = __ldg(p + 2 * GS);
        float4 xa = *(const float4*)&xt[k0 + k][0];
        float4 xb = *(const float4*)&xt[k0 + k][4];
        p += NH;
        a1[0] += w1 * xa.x; a1[1] += w1 * xa.y; a1[2] += w1 * xa.z; a1[3] += w1 * xa.w;
        a1[4] += w1 * xb.x; a1[5] += w1 * xb.y; a1[6] += w1 * xb.z; a1[7] += w1 * xb.w;
        a2[0] += w2 * xa.x; a2[1] += w2 * xa.y; a2[2] += w2 * xa.z; a2[3] += w2 * xa.w;
        a2[4] += w2 * xb.x; a2[5] += w2 * xb.y; a2[6] += w2 * xb.z; a2[7] += w2 * xb.w;
        a3[0] += w3 * xa.x; a3[1] += w3 * xa.y; a3[2] += w3 * xa.z; a3[3] += w3 * xa.w;
        a3[4] += w3 * xb.x; a3[5] += w3 * xb.y; a3[6] += w3 * xb.z; a3[7] += w3 * xb.w;
    }
}

__device__ __forceinline__ float cfc_cell(float f1, float f2, float g3) {
    float s = 1.0f / (1.0f + __expf(-g3));
    return tanhf(f1) * (1.0f - s) + s * tanhf(f2);
}

// store 3x8 partials as 6 STS.128
__device__ __forceinline__ void store_part(float (*__restrict__ P)[M],
                                           const float* a1, const float* a2,
                                           const float* a3) {
    *(float4*)&P[0][0] = make_float4(a1[0], a1[1], a1[2], a1[3]);
    *(float4*)&P[0][4] = make_float4(a1[4], a1[5], a1[6], a1[7]);
    *(float4*)&P[1][0] = make_float4(a2[0], a2[1], a2[2], a2[3]);
    *(float4*)&P[1][4] = make_float4(a2[4], a2[5], a2[6], a2[7]);
    *(float4*)&P[2][0] = make_float4(a3[0], a3[1], a3[2], a3[3]);
    *(float4*)&P[2][4] = make_float4(a3[4], a3[5], a3[6], a3[7]);
}

__global__ __launch_bounds__(BT, 1)
void ncp_main(const float* __restrict__ x, const float* __restrict__ hidden,
              const float* __restrict__ fc_w, const float* __restrict__ fc_b,
              float* __restrict__ out) {
    extern __shared__ char smem_raw[];
    SM* sm = (SM*)smem_raw;
    const int tid = threadIdx.x;
    const int lane = tid & 31;
    const int wid = tid >> 5;
    const int row0 = blockIdx.x * M;

    // ---- init ----
    for (int i = tid; i < 3 * NH0; i += BT) sm->b0[i] = g_B0[i];
    for (int i = tid; i < 3 * NH1; i += BT) sm->b1[i] = g_B1[i];
    for (int i = tid; i < 3 * NH2; i += BT) sm->b2[i] = g_B2[i];
    for (int i = tid; i < OUTD * OUTD; i += BT) {
        int mm = i >> 6, o = i & 63;
        sm->fcT[i] = __ldg(&fc_w[o * OUTD + mm]);
    }
    if (tid < OUTD) sm->fcb[tid] = fc_b[tid];
    for (int i = tid; i < M * 512; i += BT) {
        int r = i >> 9, c = i & 511;
        float v = hidden[(long long)(row0 + r) * 512 + c];
        if (c < NH0)              sm->xt0[0][DIN + c][r] = v;
        else if (c < NH0 + NH1)   sm->xt1[c][r] = v;
        else                      sm->xt2[NH1 + (c - NH0 - NH1)][r] = v;
    }
    if (tid < M) {
        sm->xt0[0][397][tid] = 0.0f; sm->xt0[0][398][tid] = 0.0f; sm->xt0[0][399][tid] = 0.0f;
        sm->xt0[1][397][tid] = 0.0f; sm->xt0[1][398][tid] = 0.0f; sm->xt0[1][399][tid] = 0.0f;
        sm->xt2[243][tid] = 0.0f;
    }
    __syncthreads();

    // ---- sequential timestep loop ----
#pragma unroll 1
    for (int t = 0; t < Tsz; ++t) {
        const int b = t & 1, nb = b ^ 1;

        // load x_t transposed into current buffer (cols < 128)
        {
            int r = tid & 7, cb = tid >> 3;
            const float* xp = x + ((long long)(row0 + r) * Tsz + t) * DIN;
#pragma unroll
            for (int u = 0; u < 4; ++u)
                sm->xt0[b][cb + 32 * u][r] = __ldg(&xp[cb + 32 * u]);
        }
        __syncthreads();

        // ===== layer 0 =====
        // main: unit j = tid (0..255), full k, fused epilogue
        {
            const int j = tid;
            float a1[M], a2[M], a3[M];
            float bf1 = sm->b0[j], bf2 = sm->b0[NH0 + j], bt = sm->b0[2 * NH0 + j];
#pragma unroll
            for (int r = 0; r < M; ++r) { a1[r] = bf1; a2[r] = bf2; a3[r] = bt; }
            gemm3<CATP0, NH0, GS0>(g_W0, j, 0, sm->xt0[b], a1, a2, a3);
            float n[M];
#pragma unroll
            for (int r = 0; r < M; ++r) n[r] = cfc_cell(a1[r], a2[r], a3[r]);
            float4 na = make_float4(n[0], n[1], n[2], n[3]);
            float4 nbv = make_float4(n[4], n[5], n[6], n[7]);
            *(float4*)&sm->xt1[j][0] = na;
            *(float4*)&sm->xt1[j][4] = nbv;
            *(float4*)&sm->xt0[nb][DIN + j][0] = na;
            *(float4*)&sm->xt0[nb][DIN + j][4] = nbv;
        }
        // tail: units j=256..268 as 8 k-chunks of 50 (warps 0..3, lanes 0..25)
        if (wid < 4 && lane < 26) {
            int s = wid * 26 + lane;           // 0..103
            int ju = s % 13, ch = s / 13;
            int j = 256 + ju, k0 = ch * 50;
            float a1[M], a2[M], a3[M];
            float bf1 = 0.f, bf2 = 0.f, bt = 0.f;
            if (ch == 0) { bf1 = sm->b0[j]; bf2 = sm->b0[NH0 + j]; bt = sm->b0[2 * NH0 + j]; }
#pragma unroll
            for (int r = 0; r < M; ++r) { a1[r] = bf1; a2[r] = bf2; a3[r] = bt; }
            gemm3<50, NH0, GS0>(g_W0, j, k0, sm->xt0[b], a1, a2, a3);
            store_part(sm->P0[ch][ju], a1, a2, a3);
        }
        __syncthreads();
        // tail reduce: 13 units x 8 rows
        if (tid < 104) {
            int ju = tid >> 3, r = tid & 7;
            float f1 = 0.f, f2 = 0.f, g3 = 0.f;
#pragma unroll
            for (int ch = 0; ch < 8; ++ch) {
                f1 += sm->P0[ch][ju][0][r];
                f2 += sm->P0[ch][ju][1][r];
                g3 += sm->P0[ch][ju][2][r];
            }
            float n = cfc_cell(f1, f2, g3);
            sm->xt1[256 + ju][r] = n;
            sm->xt0[nb][DIN + 256 + ju][r] = n;
        }
        __syncthreads();

        // ===== layer 1 ===== units (j, khalf): 358 = 256 main + 102 tail
        {
            const int u = tid;
            int j = u % NH1, kh = u / NH1, k0 = kh * 224;
            float a1[M], a2[M], a3[M];
            float bf1 = 0.f, bf2 = 0.f, bt = 0.f;
            if (kh == 0) { bf1 = sm->b1[j]; bf2 = sm->b1[NH1 + j]; bt = sm->b1[2 * NH1 + j]; }
#pragma unroll
            for (int r = 0; r < M; ++r) { a1[r] = bf1; a2[r] = bf2; a3[r] = bt; }
            gemm3<224, NH1, GS1>(g_W1, j, k0, sm->xt1, a1, a2, a3);
            store_part(sm->P1[kh][j], a1, a2, a3);
        }
        if (wid < 4 && lane < 26) {
            int u = 256 + wid * 26 + lane;
            if (u < 358) {
                int j = u - NH1;               // kh = 1 for all these
                float a1[M], a2[M], a3[M];
#pragma unroll
                for (int r = 0; r < M; ++r) { a1[r] = 0.f; a2[r] = 0.f; a3[r] = 0.f; }
                gemm3<224, NH1, GS1>(g_W1, j, 224, sm->xt1, a1, a2, a3);
                store_part(sm->P1[1][j], a1, a2, a3);
            }
        }
        __syncthreads();
        // L1 reduce + activate: 179*8 = 1432 cells
        for (int c = tid; c < NH1 * M; c += BT) {
            int j = c >> 3, r = c & 7;
            float f1 = sm->P1[0][j][0][r] + sm->P1[1][j][0][r];
            float f2 = sm->P1[0][j][1][r] + sm->P1[1][j][1][r];
            float g3 = sm->P1[0][j][2][r] + sm->P1[1][j][2][r];
            float n = cfc_cell(f1, f2, g3);
            sm->xt2[j][r] = n;
            sm->xt1[NH0 + j][r] = n;
        }
        __syncthreads();

        // ===== layer 2 ===== units (j, kq): exactly 256
        {
            int j = tid & 63, kq = tid >> 6, k0 = kq * 61;
            float a1[M], a2[M], a3[M];
            float bf1 = 0.f, bf2 = 0.f, bt = 0.f;
            if (kq == 0) { bf1 = sm->b2[j]; bf2 = sm->b2[NH2 + j]; bt = sm->b2[2 * NH2 + j]; }
#pragma unroll
            for (int r = 0; r < M; ++r) { a1[r] = bf1; a2[r] = bf2; a3[r] = bt; }
            gemm3<61, NH2, GS2>(g_W2, j, k0, sm->xt2, a1, a2, a3);
            store_part(sm->P2[kq][j], a1, a2, a3);
        }
        __syncthreads();
        // L2 reduce + activate: 64*8 = 512 cells
        for (int c = tid; c < NH2 * M; c += BT) {
            int j = c >> 3, r = c & 7;
            float f1 = sm->P2[0][j][0][r] + sm->P2[1][j][0][r]
                     + sm->P2[2][j][0][r] + sm->P2[3][j][0][r];
            float f2 = sm->P2[0][j][1][r] + sm->P2[1][j][1][r]
                     + sm->P2[2][j][1][r] + sm->P2[3][j][1][r];
            float g3 = sm->P2[0][j][2][r] + sm->P2[1][j][2][r]
                     + sm->P2[2][j][2][r] + sm->P2[3][j][2][r];
            sm->xt2[NH1 + j][r] = cfc_cell(f1, f2, g3);
        }
        __syncthreads();

        // ===== fused output projection =====
        for (int idx = tid; idx < M * OUTD; idx += BT) {
            int r = idx >> 6, o = idx & 63;
            float a = sm->fcb[o];
#pragma unroll 8
            for (int mm = 0; mm < OUTD; ++mm)
                a += sm->fcT[mm * OUTD + o] * sm->xt2[NH1 + mm][r];
            out[((long long)(row0 + r) * Tsz + t) * OUTD + o] = a;
        }
        // next iteration's x-load writes xt0[nb] cols<128 only; a barrier
        // follows before any gemm reads. No trailing barrier needed.
    }
    __syncthreads();

    // ---- final hidden state (T even -> final h0 lives in buffer 0) ----
    float* hn = out + PRED_ELEMS;
    for (int i = tid; i < M * 512; i += BT) {
        int r = i >> 9, c = i & 511;
        float v;
        if (c < NH0)            v = sm->xt0[0][DIN + c][r];
        else if (c < NH0 + NH1) v = sm->xt1[c][r];
        else                    v = sm->xt2[NH1 + (c - NH0 - NH1)][r];
        hn[(long long)(row0 + r) * 512 + c] = v;
    }
}

// ---------------- host launcher ----------------
extern "C" void kernel_launch(void* const* d_in, const int* in_sizes, int n_in,
                              void* d_out, int out_size) {
    (void)n_in; (void)out_size;
    const float* x      = (const float*)d_in[0];
    const float* hidden = (const float*)d_in[1];
    const void*  m0     = d_in[2];
    const void*  m1     = d_in[3];
    const void*  m2     = d_in[4];
    const float* ff1_w0 = (const float*)d_in[5];
    const float* ff1_b0 = (const float*)d_in[6];
    const float* ff2_w0 = (const float*)d_in[7];
    const float* ff2_b0 = (const float*)d_in[8];
    const float* ta_w0  = (const float*)d_in[9];
    const float* ta_b0  = (const float*)d_in[10];
    const float* tb_w0  = (const float*)d_in[11];
    const float* tb_b0  = (const float*)d_in[12];
    const float* ff1_w1 = (const float*)d_in[13];
    const float* ff1_b1 = (const float*)d_in[14];
    const float* ff2_w1 = (const float*)d_in[15];
    const float* ff2_b1 = (const float*)d_in[16];
    const float* ta_w1  = (const float*)d_in[17];
    const float* ta_b1  = (const float*)d_in[18];
    const float* tb_w1  = (const float*)d_in[19];
    const float* tb_b1  = (const float*)d_in[20];
    const float* ff1_w2 = (const float*)d_in[21];
    const float* ff1_b2 = (const float*)d_in[22];
    const float* ff2_w2 = (const float*)d_in[23];
    const float* ff2_b2 = (const float*)d_in[24];
    const float* ta_w2  = (const float*)d_in[25];
    const float* ta_b2  = (const float*)d_in[26];
    const float* tb_w2  = (const float*)d_in[27];
    const float* tb_b2  = (const float*)d_in[28];
    const float* fc_w   = (const float*)d_in[29];
    const float* fc_b   = (const float*)d_in[30];
    float* out = (float*)d_out;

    float *w0, *w1, *w2, *bc0, *bc1, *bc2;
    cudaGetSymbolAddress((void**)&w0, g_W0);
    cudaGetSymbolAddress((void**)&w1, g_W1);
    cudaGetSymbolAddress((void**)&w2, g_W2);
    cudaGetSymbolAddress((void**)&bc0, g_B0);
    cudaGetSymbolAddress((void**)&bc1, g_B1);
    cudaGetSymbolAddress((void**)&bc2, g_B2);

    detect_kernel<<<3, 256>>>(m0, in_sizes[2], m1, in_sizes[3], m2, in_sizes[4]);

    prep3_kernel<<<(3 * GS0 + 255) / 256, 256>>>(
        ff1_w0, ff2_w0, ta_w0, tb_w0, ff1_b0, ff2_b0, ta_b0, tb_b0,
        m0, 0, CAT0, CATP0, NH0, w0, bc0);
    prep3_kernel<<<(3 * GS1 + 255) / 256, 256>>>(
        ff1_w1, ff2_w1, ta_w1, tb_w1, ff1_b1, ff2_b1, ta_b1, tb_b1,
        m1, 1, CAT1, CATP1, NH1, w1, bc1);
    prep3_kernel<<<(3 * GS2 + 255) / 256, 256>>>(
        ff1_w2, ff2_w2, ta_w2, tb_w2, ff1_b2, ff2_b2, ta_b2, tb_b2,
        m2, 2, CAT2, CATP2, NH2, w2, bc2);

    cudaFuncSetAttribute(ncp_main, cudaFuncAttributeMaxDynamicSharedMemorySize,
                         (int)sizeof(SM));
    ncp_main<<<Bsz / M, BT, sizeof(SM)>>>(x, hidden, fc_w, fc_b, out);
}

// round 8
// speedup vs baseline: 2.1914x; 1.4057x over previous
#include <cuda_runtime.h>
#include <math.h>

#define BT 512   // threads per block (main kernel)
#define M  8     // batch rows per block

// ---------------- problem constants ----------------
constexpr int Bsz = 1024, Tsz = 256, DIN = 128;
constexpr int NH0 = 269, NH1 = 179, NH2 = 64;
constexpr int CAT0 = DIN + NH0;   // 397
constexpr int CAT1 = NH0 + NH1;   // 448
constexpr int CAT2 = NH1 + NH2;   // 243
constexpr int CATP0 = 400, CATP1 = 448, CATP2 = 244;  // padded k
constexpr int OUTD = 64;
constexpr long long PRED_ELEMS = (long long)Bsz * Tsz * OUTD;

// gate strides in the per-gate weight arrays
constexpr int GS0 = CATP0 * NH0;   // 107600
constexpr int GS1 = CATP1 * NH1;   // 80192
constexpr int GS2 = CATP2 * NH2;   // 15616

// ---------------- device scratch ----------------
__device__ float g_W0[3 * GS0];   // [gate][k][j], gates: ff1, ff2, ta+tb
__device__ float g_W1[3 * GS1];
__device__ float g_W2[3 * GS2];
__device__ float g_B0[3 * NH0];
__device__ float g_B1[3 * NH1];
__device__ float g_B2[3 * NH2];
__device__ int   g_fmt[3];

// ---------------- mask dtype detection (unchanged, known-good) ----------------
__global__ void detect_kernel(const void* m0, int n0, const void* m1, int n1,
                              const void* m2, int n2) {
    const void* p = (blockIdx.x == 0) ? m0 : (blockIdx.x == 1) ? m1 : m2;
    int n = (blockIdx.x == 0) ? n0 : (blockIdx.x == 1) ? n1 : n2;
    __shared__ int fl;
    if (threadIdx.x == 0) fl = 0;
    __syncthreads();
    int nw = n >> 2;
    const unsigned* w = (const unsigned*)p;
    int loc = 0;
    for (int i = threadIdx.x; i < nw; i += blockDim.x) {
        unsigned v = w[i];
        if (v == 0x3F800000u) loc |= 1;
        else if (v == 0x3F803F80u || v == 0x00003F80u) loc |= 2;
        else if (v != 0u && v != 1u) loc |= 4;
    }
    atomicOr(&fl, loc);
    __syncthreads();
    if (threadIdx.x == 0) {
        int f = fl, fmt;
        if (f & 2) fmt = 3;
        else if (f & 1) fmt = 0;
        else if (f & 4) fmt = 2;
        else fmt = 1;
        g_fmt[blockIdx.x] = fmt;
    }
}

__device__ __forceinline__ bool maskbit(const void* p, int fmt, int idx) {
    switch (fmt) {
        case 0: return ((const float*)p)[idx] != 0.0f;
        case 1: return ((const int*)p)[idx] != 0;
        case 3: return ((const unsigned short*)p)[idx] != 0;
        default: return ((const unsigned char*)p)[idx] != 0;
    }
}

// ---------------- fused weight prep (all 3 layers, one launch) ----------------
__device__ __forceinline__ void prep_elem(
    long long idx, const float* w1, const float* w2,
    const float* wa, const float* wb,
    const float* b1, const float* b2, const float* ba, const float* bb,
    const void* mask, int fmt, int CAT, int CATP, int NH,
    float* W, float* Bc) {
    long long per = (long long)CATP * NH;
    int g = (int)(idx / per);
    long long rem = idx - (long long)g * per;
    int k = (int)(rem / NH);
    int j = (int)(rem - (long long)k * NH);
    float v = 0.0f;
    if (k < CAT) {
        if (g == 2) {
            v = wa[j * CAT + k] + wb[j * CAT + k];
        } else {
            v = (g == 0) ? w1[j * CAT + k] : w2[j * CAT + k];
            if (!maskbit(mask, fmt, j * CAT + k)) v = 0.0f;
        }
    }
    W[idx] = v;
    if (k == 0)
        Bc[g * NH + j] = (g == 0) ? b1[j] : (g == 1) ? b2[j] : (ba[j] + bb[j]);
}

__global__ void prep_all(
    const float* f10, const float* f20, const float* ta0, const float* tb0,
    const float* b10, const float* b20, const float* ba0, const float* bb0,
    const float* f11, const float* f21, const float* ta1, const float* tb1,
    const float* b11, const float* b21, const float* ba1, const float* bb1,
    const float* f12, const float* f22, const float* ta2, const float* tb2,
    const float* b12, const float* b22, const float* ba2, const float* bb2,
    const void* m0, const void* m1, const void* m2) {
    const long long N0 = 3LL * GS0, N1 = 3LL * GS1, N2 = 3LL * GS2;
    const long long total = N0 + N1 + N2;
    for (long long idx = (long long)blockIdx.x * blockDim.x + threadIdx.x;
         idx < total; idx += (long long)gridDim.x * blockDim.x) {
        if (idx < N0) {
            prep_elem(idx, f10, f20, ta0, tb0, b10, b20, ba0, bb0,
                      m0, g_fmt[0], CAT0, CATP0, NH0, g_W0, g_B0);
        } else if (idx < N0 + N1) {
            prep_elem(idx - N0, f11, f21, ta1, tb1, b11, b21, ba1, bb1,
                      m1, g_fmt[1], CAT1, CATP1, NH1, g_W1, g_B1);
        } else {
            prep_elem(idx - N0 - N1, f12, f22, ta2, tb2, b12, b22, ba2, bb2,
                      m2, g_fmt[2], CAT2, CATP2, NH2, g_W2, g_B2);
        }
    }
}

// ---------------- main persistent kernel ----------------
struct SM {
    float xt0[2][CATP0][M];       // [buf][ x(128) | h0(269) | pad ]
    float xt1[CATP1][M];          // [ n0(269) | h1(179) ]
    float xt2[CATP2][M];          // [ n1(179) | h2(64) | pad ]
    union {
        struct { float m[2][256][3][M]; float x[8][13][3][M]; } p0;
        struct { float m[3][179][3][M]; float x[4][25][3][M]; } p1;
        float p2[8][64][3][M];
    } P;
    float fcT[OUTD * OUTD];       // fcT[m*64+o] = fc_w[o][m]
    float fcb[OUTD];
    float b0[3 * NH0];
    float b1[3 * NH1];
    float b2[3 * NH2];
};

#define FMA_BODY()                                                             \
    do {                                                                       \
        float w1 = __ldg(p);                                                   \
        float w2 = __ldg(p + GS);                                              \
        float w3 = __ldg(p + 2 * GS);                                          \
        float4 xa = *(const float4*)xp;                                        \
        float4 xb = *(const float4*)(xp + 4);                                  \
        p += NH; xp += M;                                                      \
        a1[0] += w1 * xa.x; a1[1] += w1 * xa.y; a1[2] += w1 * xa.z;            \
        a1[3] += w1 * xa.w; a1[4] += w1 * xb.x; a1[5] += w1 * xb.y;            \
        a1[6] += w1 * xb.z; a1[7] += w1 * xb.w;                                \
        a2[0] += w2 * xa.x; a2[1] += w2 * xa.y; a2[2] += w2 * xa.z;            \
        a2[3] += w2 * xa.w; a2[4] += w2 * xb.x; a2[5] += w2 * xb.y;            \
        a2[6] += w2 * xb.z; a2[7] += w2 * xb.w;                                \
        a3[0] += w3 * xa.x; a3[1] += w3 * xa.y; a3[2] += w3 * xa.z;            \
        a3[3] += w3 * xa.w; a3[4] += w3 * xb.x; a3[5] += w3 * xb.y;            \
        a3[6] += w3 * xb.z; a3[7] += w3 * xb.w;                                \
    } while (0)

template <int KLEN, int NH, int GS>
__device__ __forceinline__ void gemm3_t(const float* __restrict__ W, int j, int k0,
                                        const float (*__restrict__ xt)[M],
                                        float* __restrict__ a1,
                                        float* __restrict__ a2,
                                        float* __restrict__ a3) {
    const float* p = W + (size_t)k0 * NH + j;
    const float* xp = &xt[k0][0];
#pragma unroll 4
    for (int k = 0; k < KLEN; ++k) FMA_BODY();
}

template <int NH, int GS>
__device__ __forceinline__ void gemm3_rt(const float* __restrict__ W, int j, int k0,
                                         int klen,
                                         const float (*__restrict__ xt)[M],
                                         float* __restrict__ a1,
                                         float* __restrict__ a2,
                                         float* __restrict__ a3) {
    const float* p = W + (size_t)k0 * NH + j;
    const float* xp = &xt[k0][0];
#pragma unroll 4
    for (int k = 0; k < klen; ++k) FMA_BODY();
}

__device__ __forceinline__ float cfc_cell(float f1, float f2, float g3) {
    float s = 1.0f / (1.0f + __expf(-g3));
    return tanhf(f1) * (1.0f - s) + s * tanhf(f2);
}

__device__ __forceinline__ void store_part(float (*__restrict__ P)[M],
                                           const float* a1, const float* a2,
                                           const float* a3) {
    *(float4*)&P[0][0] = make_float4(a1[0], a1[1], a1[2], a1[3]);
    *(float4*)&P[0][4] = make_float4(a1[4], a1[5], a1[6], a1[7]);
    *(float4*)&P[1][0] = make_float4(a2[0], a2[1], a2[2], a2[3]);
    *(float4*)&P[1][4] = make_float4(a2[4], a2[5], a2[6], a2[7]);
    *(float4*)&P[2][0] = make_float4(a3[0], a3[1], a3[2], a3[3]);
    *(float4*)&P[2][4] = make_float4(a3[4], a3[5], a3[6], a3[7]);
}

__global__ __launch_bounds__(BT, 1)
void ncp_main(const float* __restrict__ x, const float* __restrict__ hidden,
              const float* __restrict__ fc_w, const float* __restrict__ fc_b,
              float* __restrict__ out) {
    extern __shared__ char smem_raw[];
    SM* sm = (SM*)smem_raw;
    const int tid = threadIdx.x;
    const int lane = tid & 31;
    const int wid = tid >> 5;
    const int row0 = blockIdx.x * M;
    const int xr = tid & 7, xc = tid >> 3;   // x-load mapping: row, col (0..63)

    // ---- init ----
    for (int i = tid; i < 3 * NH0; i += BT) sm->b0[i] = g_B0[i];
    for (int i = tid; i < 3 * NH1; i += BT) sm->b1[i] = g_B1[i];
    for (int i = tid; i < 3 * NH2; i += BT) sm->b2[i] = g_B2[i];
    for (int i = tid; i < OUTD * OUTD; i += BT) {
        int mm = i >> 6, o = i & 63;
        sm->fcT[i] = __ldg(&fc_w[o * OUTD + mm]);
    }
    if (tid < OUTD) sm->fcb[tid] = fc_b[tid];
    for (int i = tid; i < M * 512; i += BT) {
        int r = i >> 9, c = i & 511;
        float v = hidden[(long long)(row0 + r) * 512 + c];
        if (c < NH0)              sm->xt0[0][DIN + c][r] = v;
        else if (c < NH0 + NH1)   sm->xt1[c][r] = v;
        else                      sm->xt2[NH1 + (c - NH0 - NH1)][r] = v;
    }
    if (tid < M) {
        sm->xt0[0][397][tid] = 0.0f; sm->xt0[0][398][tid] = 0.0f; sm->xt0[0][399][tid] = 0.0f;
        sm->xt0[1][397][tid] = 0.0f; sm->xt0[1][398][tid] = 0.0f; sm->xt0[1][399][tid] = 0.0f;
        sm->xt2[243][tid] = 0.0f;
    }
    // preload x(0) into buffer 0
    {
        const float* xp = x + ((long long)(row0 + xr) * Tsz + 0) * DIN;
        sm->xt0[0][xc][xr]      = __ldg(&xp[xc]);
        sm->xt0[0][xc + 64][xr] = __ldg(&xp[xc + 64]);
    }
    __syncthreads();

    // ---- sequential timestep loop ----
#pragma unroll 1
    for (int t = 0; t < Tsz; ++t) {
        const int b = t & 1, nb = b ^ 1;

        // prefetch x(t+1) into registers (consumed in FC phase)
        float rx0 = 0.f, rx1 = 0.f;
        if (t + 1 < Tsz) {
            const float* xp = x + ((long long)(row0 + xr) * Tsz + (t + 1)) * DIN;
            rx0 = __ldg(&xp[xc]);
            rx1 = __ldg(&xp[xc + 64]);
        }

        // ===== layer 0 gemm ===== units: (j<256) x (kh in {0,1}), K=200 each
        {
            const int kh = tid >> 8, jj = tid & 255;
            float a1[M], a2[M], a3[M];
            float bf1 = 0.f, bf2 = 0.f, bt = 0.f;
            if (kh == 0) { bf1 = sm->b0[jj]; bf2 = sm->b0[NH0 + jj]; bt = sm->b0[2 * NH0 + jj]; }
#pragma unroll
            for (int r = 0; r < M; ++r) { a1[r] = bf1; a2[r] = bf2; a3[r] = bt; }
            gemm3_t<200, NH0, GS0>(g_W0, jj, kh * 200, sm->xt0[b], a1, a2, a3);
            store_part(sm->P.p0.m[kh][jj], a1, a2, a3);
        }
        // tail: j=256..268 full-K as 8 chunks of 50 (one warp per SMSP)
        if (wid < 4 && lane < 26) {
            int s = wid * 26 + lane;           // 0..103
            int ju = s % 13, ch = s / 13;
            int j = 256 + ju;
            float a1[M], a2[M], a3[M];
            float bf1 = 0.f, bf2 = 0.f, bt = 0.f;
            if (ch == 0) { bf1 = sm->b0[j]; bf2 = sm->b0[NH0 + j]; bt = sm->b0[2 * NH0 + j]; }
#pragma unroll
            for (int r = 0; r < M; ++r) { a1[r] = bf1; a2[r] = bf2; a3[r] = bt; }
            gemm3_t<50, NH0, GS0>(g_W0, j, ch * 50, sm->xt0[b], a1, a2, a3);
            store_part(sm->P.p0.x[ch][ju], a1, a2, a3);
        }
        __syncthreads();

        // ===== layer 0 reduce + activate ===== 269*8 cells
        for (int c = tid; c < NH0 * M; c += BT) {
            int j = c >> 3, r = c & 7;
            float f1, f2, g3;
            if (j < 256) {
                f1 = sm->P.p0.m[0][j][0][r] + sm->P.p0.m[1][j][0][r];
                f2 = sm->P.p0.m[0][j][1][r] + sm->P.p0.m[1][j][1][r];
                g3 = sm->P.p0.m[0][j][2][r] + sm->P.p0.m[1][j][2][r];
            } else {
                int ju = j - 256;
                f1 = 0.f; f2 = 0.f; g3 = 0.f;
#pragma unroll
                for (int ch = 0; ch < 8; ++ch) {
                    f1 += sm->P.p0.x[ch][ju][0][r];
                    f2 += sm->P.p0.x[ch][ju][1][r];
                    g3 += sm->P.p0.x[ch][ju][2][r];
                }
            }
            float n = cfc_cell(f1, f2, g3);
            sm->xt1[j][r] = n;
            sm->xt0[nb][DIN + j][r] = n;
        }
        __syncthreads();

        // ===== layer 1 gemm ===== units (j, ks in {0,1,2}), K = 150/150/148
        {
            int ks = tid / NH1;                // 0..2 (tid<512 -> ks=2 has j<154)
            int j = tid - ks * NH1;
            int klen = (ks < 2) ? 150 : 148;
            float a1[M], a2[M], a3[M];
            float bf1 = 0.f, bf2 = 0.f, bt = 0.f;
            if (ks == 0) { bf1 = sm->b1[j]; bf2 = sm->b1[NH1 + j]; bt = sm->b1[2 * NH1 + j]; }
#pragma unroll
            for (int r = 0; r < M; ++r) { a1[r] = bf1; a2[r] = bf2; a3[r] = bt; }
            gemm3_rt<NH1, GS1>(g_W1, j, ks * 150, klen, sm->xt1, a1, a2, a3);
            store_part(sm->P.p1.m[ks][j], a1, a2, a3);
        }
        // tail: ks=2, j=154..178 as 4 chunks of 37 (one warp per SMSP)
        if (wid < 4 && lane < 25) {
            int ch = wid, jx = lane;           // 4 x 25
            int j = 154 + jx;
            float a1[M], a2[M], a3[M];
#pragma unroll
            for (int r = 0; r < M; ++r) { a1[r] = 0.f; a2[r] = 0.f; a3[r] = 0.f; }
            gemm3_t<37, NH1, GS1>(g_W1, j, 300 + ch * 37, sm->xt1, a1, a2, a3);
            store_part(sm->P.p1.x[ch][jx], a1, a2, a3);
        }
        __syncthreads();

        // ===== layer 1 reduce + activate ===== 179*8 cells
        for (int c = tid; c < NH1 * M; c += BT) {
            int j = c >> 3, r = c & 7;
            float f1 = sm->P.p1.m[0][j][0][r] + sm->P.p1.m[1][j][0][r];
            float f2 = sm->P.p1.m[0][j][1][r] + sm->P.p1.m[1][j][1][r];
            float g3 = sm->P.p1.m[0][j][2][r] + sm->P.p1.m[1][j][2][r];
            if (j < 154) {
                f1 += sm->P.p1.m[2][j][0][r];
                f2 += sm->P.p1.m[2][j][1][r];
                g3 += sm->P.p1.m[2][j][2][r];
            } else {
                int jx = j - 154;
#pragma unroll
                for (int ch = 0; ch < 4; ++ch) {
                    f1 += sm->P.p1.x[ch][jx][0][r];
                    f2 += sm->P.p1.x[ch][jx][1][r];
                    g3 += sm->P.p1.x[ch][jx][2][r];
                }
            }
            float n = cfc_cell(f1, f2, g3);
            sm->xt2[j][r] = n;
            sm->xt1[NH0 + j][r] = n;
        }
        __syncthreads();

        // ===== layer 2 gemm ===== units (j, kq in 0..7), K = 31/31/31/31/30/30/30/30
        {
            int kq = tid >> 6, j = tid & 63;
            float a1[M], a2[M], a3[M];
            float bf1 = 0.f, bf2 = 0.f, bt = 0.f;
            if (kq == 0) { bf1 = sm->b2[j]; bf2 = sm->b2[NH2 + j]; bt = sm->b2[2 * NH2 + j]; }
#pragma unroll
            for (int r = 0; r < M; ++r) { a1[r] = bf1; a2[r] = bf2; a3[r] = bt; }
            if (kq < 4)
                gemm3_t<31, NH2, GS2>(g_W2, j, kq * 31, sm->xt2, a1, a2, a3);
            else
                gemm3_t<30, NH2, GS2>(g_W2, j, 124 + (kq - 4) * 30, sm->xt2, a1, a2, a3);
            store_part(sm->P.p2[kq][j], a1, a2, a3);
        }
        __syncthreads();

        // ===== layer 2 reduce + activate ===== 64*8 = 512 cells, one per thread
        {
            int j = tid >> 3, r = tid & 7;
            float f1 = 0.f, f2 = 0.f, g3 = 0.f;
#pragma unroll
            for (int kq = 0; kq < 8; ++kq) {
                f1 += sm->P.p2[kq][j][0][r];
                f2 += sm->P.p2[kq][j][1][r];
                g3 += sm->P.p2[kq][j][2][r];
            }
            sm->xt2[NH1 + j][r] = cfc_cell(f1, f2, g3);
        }
        __syncthreads();

        // ===== fused output projection + x(t+1) store =====
        {
            int r = tid >> 6, o = tid & 63;
            float a = sm->fcb[o];
#pragma unroll 8
            for (int mm = 0; mm < OUTD; ++mm)
                a += sm->fcT[mm * OUTD + o] * sm->xt2[NH1 + mm][r];
            out[((long long)(row0 + r) * Tsz + t) * OUTD + o] = a;
        }
        if (t + 1 < Tsz) {
            sm->xt0[nb][xc][xr]      = rx0;
            sm->xt0[nb][xc + 64][xr] = rx1;
        }
        __syncthreads();
    }

    // ---- final hidden state (Tsz even -> final h0 in buffer 0) ----
    float* hn = out + PRED_ELEMS;
    for (int i = tid; i < M * 512; i += BT) {
        int r = i >> 9, c = i & 511;
        float v;
        if (c < NH0)            v = sm->xt0[0][DIN + c][r];
        else if (c < NH0 + NH1) v = sm->xt1[c][r];
        else                    v = sm->xt2[NH1 + (c - NH0 - NH1)][r];
        hn[(long long)(row0 + r) * 512 + c] = v;
    }
}

// ---------------- host launcher ----------------
extern "C" void kernel_launch(void* const* d_in, const int* in_sizes, int n_in,
                              void* d_out, int out_size) {
    (void)n_in; (void)out_size;
    const float* x      = (const float*)d_in[0];
    const float* hidden = (const float*)d_in[1];
    const void*  m0     = d_in[2];
    const void*  m1     = d_in[3];
    const void*  m2     = d_in[4];
    const float* ff1_w0 = (const float*)d_in[5];
    const float* ff1_b0 = (const float*)d_in[6];
    const float* ff2_w0 = (const float*)d_in[7];
    const float* ff2_b0 = (const float*)d_in[8];
    const float* ta_w0  = (const float*)d_in[9];
    const float* ta_b0  = (const float*)d_in[10];
    const float* tb_w0  = (const float*)d_in[11];
    const float* tb_b0  = (const float*)d_in[12];
    const float* ff1_w1 = (const float*)d_in[13];
    const float* ff1_b1 = (const float*)d_in[14];
    const float* ff2_w1 = (const float*)d_in[15];
    const float* ff2_b1 = (const float*)d_in[16];
    const float* ta_w1  = (const float*)d_in[17];
    const float* ta_b1  = (const float*)d_in[18];
    const float* tb_w1  = (const float*)d_in[19];
    const float* tb_b1  = (const float*)d_in[20];
    const float* ff1_w2 = (const float*)d_in[21];
    const float* ff1_b2 = (const float*)d_in[22];
    const float* ff2_w2 = (const float*)d_in[23];
    const float* ff2_b2 = (const float*)d_in[24];
    const float* ta_w2  = (const float*)d_in[25];
    const float* ta_b2  = (const float*)d_in[26];
    const float* tb_w2  = (const float*)d_in[27];
    const float* tb_b2  = (const float*)d_in[28];
    const float* fc_w   = (const float*)d_in[29];
    const float* fc_b   = (const float*)d_in[30];
    float* out = (float*)d_out;

    detect_kernel<<<3, 256>>>(m0, in_sizes[2], m1, in_sizes[3], m2, in_sizes[4]);

    prep_all<<<1024, 256>>>(
        ff1_w0, ff2_w0, ta_w0, tb_w0, ff1_b0, ff2_b0, ta_b0, tb_b0,
        ff1_w1, ff2_w1, ta_w1, tb_w1, ff1_b1, ff2_b1, ta_b1, tb_b1,
        ff1_w2, ff2_w2, ta_w2, tb_w2, ff1_b2, ff2_b2, ta_b2, tb_b2,
        m0, m1, m2);

    cudaFuncSetAttribute(ncp_main, cudaFuncAttributeMaxDynamicSharedMemorySize,
                         (int)sizeof(SM));
    ncp_main<<<Bsz / M, BT, sizeof(SM)>>>(x, hidden, fc_w, fc_b, out);
}

// round 9
// speedup vs baseline: 2.2330x; 1.0190x over previous
#include <cuda_runtime.h>
#include <math.h>

#define BT 512   // threads per block (main kernel)
#define M  8     // batch rows per block

// ---------------- problem constants ----------------
constexpr int Bsz = 1024, Tsz = 256, DIN = 128;
constexpr int NH0 = 269, NH1 = 179, NH2 = 64;
constexpr int CAT0 = DIN + NH0;   // 397
constexpr int CAT1 = NH0 + NH1;   // 448
constexpr int CAT2 = NH1 + NH2;   // 243
constexpr int CATP0 = 400, CATP1 = 448, CATP2 = 244;  // padded k
constexpr int OUTD = 64;
constexpr long long PRED_ELEMS = (long long)Bsz * Tsz * OUTD;

// gate strides in the per-gate weight arrays
constexpr int GS0 = CATP0 * NH0;   // 107600
constexpr int GS1 = CATP1 * NH1;   // 80192
constexpr int GS2 = CATP2 * NH2;   // 15616

// L0 tail: 13 units x 25 chunks of 16 k
constexpr int T0_CH = 25, T0_KL = 16;
// L1 tail: 25 units x 13 chunks (12 of len 12 + 1 of len 4)
constexpr int T1_CH = 13, T1_KL = 12;

// ---------------- device scratch ----------------
__device__ float g_W0[3 * GS0];   // [gate][k][j], gates: ff1, ff2, ta+tb
__device__ float g_W1[3 * GS1];
__device__ float g_W2[3 * GS2];
__device__ float g_B0[3 * NH0];
__device__ float g_B1[3 * NH1];
__device__ float g_B2[3 * NH2];
__device__ int   g_fmt[3];

// ---------------- mask dtype detection (unchanged, known-good) ----------------
__global__ void detect_kernel(const void* m0, int n0, const void* m1, int n1,
                              const void* m2, int n2) {
    const void* p = (blockIdx.x == 0) ? m0 : (blockIdx.x == 1) ? m1 : m2;
    int n = (blockIdx.x == 0) ? n0 : (blockIdx.x == 1) ? n1 : n2;
    __shared__ int fl;
    if (threadIdx.x == 0) fl = 0;
    __syncthreads();
    int nw = n >> 2;
    const unsigned* w = (const unsigned*)p;
    int loc = 0;
    for (int i = threadIdx.x; i < nw; i += blockDim.x) {
        unsigned v = w[i];
        if (v == 0x3F800000u) loc |= 1;
        else if (v == 0x3F803F80u || v == 0x00003F80u) loc |= 2;
        else if (v != 0u && v != 1u) loc |= 4;
    }
    atomicOr(&fl, loc);
    __syncthreads();
    if (threadIdx.x == 0) {
        int f = fl, fmt;
        if (f & 2) fmt = 3;
        else if (f & 1) fmt = 0;
        else if (f & 4) fmt = 2;
        else fmt = 1;
        g_fmt[blockIdx.x] = fmt;
    }
}

__device__ __forceinline__ bool maskbit(const void* p, int fmt, int idx) {
    switch (fmt) {
        case 0: return ((const float*)p)[idx] != 0.0f;
        case 1: return ((const int*)p)[idx] != 0;
        case 3: return ((const unsigned short*)p)[idx] != 0;
        default: return ((const unsigned char*)p)[idx] != 0;
    }
}

// ---------------- fused weight prep (all 3 layers, one launch) ----------------
__device__ __forceinline__ void prep_elem(
    long long idx, const float* w1, const float* w2,
    const float* wa, const float* wb,
    const float* b1, const float* b2, const float* ba, const float* bb,
    const void* mask, int fmt, int CAT, int CATP, int NH,
    float* W, float* Bc) {
    long long per = (long long)CATP * NH;
    int g = (int)(idx / per);
    long long rem = idx - (long long)g * per;
    int k = (int)(rem / NH);
    int j = (int)(rem - (long long)k * NH);
    float v = 0.0f;
    if (k < CAT) {
        if (g == 2) {
            v = wa[j * CAT + k] + wb[j * CAT + k];
        } else {
            v = (g == 0) ? w1[j * CAT + k] : w2[j * CAT + k];
            if (!maskbit(mask, fmt, j * CAT + k)) v = 0.0f;
        }
    }
    W[idx] = v;
    if (k == 0)
        Bc[g * NH + j] = (g == 0) ? b1[j] : (g == 1) ? b2[j] : (ba[j] + bb[j]);
}

__global__ void prep_all(
    const float* f10, const float* f20, const float* ta0, const float* tb0,
    const float* b10, const float* b20, const float* ba0, const float* bb0,
    const float* f11, const float* f21, const float* ta1, const float* tb1,
    const float* b11, const float* b21, const float* ba1, const float* bb1,
    const float* f12, const float* f22, const float* ta2, const float* tb2,
    const float* b12, const float* b22, const float* ba2, const float* bb2,
    const void* m0, const void* m1, const void* m2) {
    const long long N0 = 3LL * GS0, N1 = 3LL * GS1, N2 = 3LL * GS2;
    const long long total = N0 + N1 + N2;
    for (long long idx = (long long)blockIdx.x * blockDim.x + threadIdx.x;
         idx < total; idx += (long long)gridDim.x * blockDim.x) {
        if (idx < N0) {
            prep_elem(idx, f10, f20, ta0, tb0, b10, b20, ba0, bb0,
                      m0, g_fmt[0], CAT0, CATP0, NH0, g_W0, g_B0);
        } else if (idx < N0 + N1) {
            prep_elem(idx - N0, f11, f21, ta1, tb1, b11, b21, ba1, bb1,
                      m1, g_fmt[1], CAT1, CATP1, NH1, g_W1, g_B1);
        } else {
            prep_elem(idx - N0 - N1, f12, f22, ta2, tb2, b12, b22, ba2, bb2,
                      m2, g_fmt[2], CAT2, CATP2, NH2, g_W2, g_B2);
        }
    }
}

// ---------------- main persistent kernel ----------------
struct SM {
    float xt0[2][CATP0][M];       // [buf][ x(128) | h0(269) | pad ]
    float xt1[CATP1][M];          // [ n0(269) | h1(179) ]
    float xt2[CATP2][M];          // [ n1(179) | h2(64) | pad ]
    union {
        struct { float m[2][256][3][M]; float x[T0_CH][13][3][M]; } p0;
        struct { float m[3][179][3][M]; float x[T1_CH][25][3][M]; } p1;
        float p2[8][64][3][M];
    } P;
    float fcT[OUTD * OUTD];       // fcT[m*64+o] = fc_w[o][m]
    float fcb[OUTD];
    float b0[3 * NH0];
    float b1[3 * NH1];
    float b2[3 * NH2];
};

#define FMA_BODY()                                                             \
    do {                                                                       \
        float w1 = __ldg(p);                                                   \
        float w2 = __ldg(p + GS);                                              \
        float w3 = __ldg(p + 2 * GS);                                          \
        float4 xa = *(const float4*)xp;                                        \
        float4 xb = *(const float4*)(xp + 4);                                  \
        p += NH; xp += M;                                                      \
        a1[0] += w1 * xa.x; a1[1] += w1 * xa.y; a1[2] += w1 * xa.z;            \
        a1[3] += w1 * xa.w; a1[4] += w1 * xb.x; a1[5] += w1 * xb.y;            \
        a1[6] += w1 * xb.z; a1[7] += w1 * xb.w;                                \
        a2[0] += w2 * xa.x; a2[1] += w2 * xa.y; a2[2] += w2 * xa.z;            \
        a2[3] += w2 * xa.w; a2[4] += w2 * xb.x; a2[5] += w2 * xb.y;            \
        a2[6] += w2 * xb.z; a2[7] += w2 * xb.w;                                \
        a3[0] += w3 * xa.x; a3[1] += w3 * xa.y; a3[2] += w3 * xa.z;            \
        a3[3] += w3 * xa.w; a3[4] += w3 * xb.x; a3[5] += w3 * xb.y;            \
        a3[6] += w3 * xb.z; a3[7] += w3 * xb.w;                                \
    } while (0)

template <int KLEN, int NH, int GS>
__device__ __forceinline__ void gemm3_t(const float* __restrict__ W, int j, int k0,
                                        const float (*__restrict__ xt)[M],
                                        float* __restrict__ a1,
                                        float* __restrict__ a2,
                                        float* __restrict__ a3) {
    const float* p = W + (size_t)k0 * NH + j;
    const float* xp = &xt[k0][0];
#pragma unroll 4
    for (int k = 0; k < KLEN; ++k) FMA_BODY();
}

template <int NH, int GS>
__device__ __forceinline__ void gemm3_rt(const float* __restrict__ W, int j, int k0,
                                         int klen,
                                         const float (*__restrict__ xt)[M],
                                         float* __restrict__ a1,
                                         float* __restrict__ a2,
                                         float* __restrict__ a3) {
    const float* p = W + (size_t)k0 * NH + j;
    const float* xp = &xt[k0][0];
#pragma unroll 4
    for (int k = 0; k < klen; ++k) FMA_BODY();
}

__device__ __forceinline__ float cfc_cell(float f1, float f2, float g3) {
    float s = 1.0f / (1.0f + __expf(-g3));
    return tanhf(f1) * (1.0f - s) + s * tanhf(f2);
}

__device__ __forceinline__ void store_part(float (*__restrict__ P)[M],
                                           const float* a1, const float* a2,
                                           const float* a3) {
    *(float4*)&P[0][0] = make_float4(a1[0], a1[1], a1[2], a1[3]);
    *(float4*)&P[0][4] = make_float4(a1[4], a1[5], a1[6], a1[7]);
    *(float4*)&P[1][0] = make_float4(a2[0], a2[1], a2[2], a2[3]);
    *(float4*)&P[1][4] = make_float4(a2[4], a2[5], a2[6], a2[7]);
    *(float4*)&P[2][0] = make_float4(a3[0], a3[1], a3[2], a3[3]);
    *(float4*)&P[2][4] = make_float4(a3[4], a3[5], a3[6], a3[7]);
}

__global__ __launch_bounds__(BT, 1)
void ncp_main(const float* __restrict__ x, const float* __restrict__ hidden,
              const float* __restrict__ fc_w, const float* __restrict__ fc_b,
              float* __restrict__ out) {
    extern __shared__ char smem_raw[];
    SM* sm = (SM*)smem_raw;
    const int tid = threadIdx.x;
    const int row0 = blockIdx.x * M;
    const int xr = tid & 7, xc = tid >> 3;   // x-load mapping: row, col (0..63)

    // ---- init ----
    for (int i = tid; i < 3 * NH0; i += BT) sm->b0[i] = g_B0[i];
    for (int i = tid; i < 3 * NH1; i += BT) sm->b1[i] = g_B1[i];
    for (int i = tid; i < 3 * NH2; i += BT) sm->b2[i] = g_B2[i];
    for (int i = tid; i < OUTD * OUTD; i += BT) {
        int mm = i >> 6, o = i & 63;
        sm->fcT[i] = __ldg(&fc_w[o * OUTD + mm]);
    }
    if (tid < OUTD) sm->fcb[tid] = fc_b[tid];
    for (int i = tid; i < M * 512; i += BT) {
        int r = i >> 9, c = i & 511;
        float v = hidden[(long long)(row0 + r) * 512 + c];
        if (c < NH0)              sm->xt0[0][DIN + c][r] = v;
        else if (c < NH0 + NH1)   sm->xt1[c][r] = v;
        else                      sm->xt2[NH1 + (c - NH0 - NH1)][r] = v;
    }
    if (tid < M) {
        sm->xt0[0][397][tid] = 0.0f; sm->xt0[0][398][tid] = 0.0f; sm->xt0[0][399][tid] = 0.0f;
        sm->xt0[1][397][tid] = 0.0f; sm->xt0[1][398][tid] = 0.0f; sm->xt0[1][399][tid] = 0.0f;
        sm->xt2[243][tid] = 0.0f;
    }
    // preload x(0) into buffer 0
    {
        const float* xp = x + ((long long)(row0 + xr) * Tsz + 0) * DIN;
        sm->xt0[0][xc][xr]      = __ldg(&xp[xc]);
        sm->xt0[0][xc + 64][xr] = __ldg(&xp[xc + 64]);
    }
    __syncthreads();

    // ---- sequential timestep loop ----
#pragma unroll 1
    for (int t = 0; t < Tsz; ++t) {
        const int b = t & 1, nb = b ^ 1;

        // prefetch x(t+1) into registers (consumed in FC phase)
        float rx0 = 0.f, rx1 = 0.f;
        if (t + 1 < Tsz) {
            const float* xp = x + ((long long)(row0 + xr) * Tsz + (t + 1)) * DIN;
            rx0 = __ldg(&xp[xc]);
            rx1 = __ldg(&xp[xc + 64]);
        }

        // ===== layer 0 gemm ===== units: (j<256) x (kh in {0,1}), K=200 each
        {
            const int kh = tid >> 8, jj = tid & 255;
            float a1[M], a2[M], a3[M];
            float bf1 = 0.f, bf2 = 0.f, bt = 0.f;
            if (kh == 0) { bf1 = sm->b0[jj]; bf2 = sm->b0[NH0 + jj]; bt = sm->b0[2 * NH0 + jj]; }
#pragma unroll
            for (int r = 0; r < M; ++r) { a1[r] = bf1; a2[r] = bf2; a3[r] = bt; }
            gemm3_t<200, NH0, GS0>(g_W0, jj, kh * 200, sm->xt0[b], a1, a2, a3);
            store_part(sm->P.p0.m[kh][jj], a1, a2, a3);
        }
        // tail: j=256..268, K=400 as 25 chunks of 16 spread over 325 threads
        if (tid < 13 * T0_CH) {
            int ju = tid % 13, ch = tid / 13;
            int j = 256 + ju;
            float a1[M], a2[M], a3[M];
            float bf1 = 0.f, bf2 = 0.f, bt = 0.f;
            if (ch == 0) { bf1 = sm->b0[j]; bf2 = sm->b0[NH0 + j]; bt = sm->b0[2 * NH0 + j]; }
#pragma unroll
            for (int r = 0; r < M; ++r) { a1[r] = bf1; a2[r] = bf2; a3[r] = bt; }
            gemm3_t<T0_KL, NH0, GS0>(g_W0, j, ch * T0_KL, sm->xt0[b], a1, a2, a3);
            store_part(sm->P.p0.x[ch][ju], a1, a2, a3);
        }
        __syncthreads();

        // ===== layer 0 reduce + activate ===== 269*8 cells
        for (int c = tid; c < NH0 * M; c += BT) {
            int j = c >> 3, r = c & 7;
            float f1, f2, g3;
            if (j < 256) {
                f1 = sm->P.p0.m[0][j][0][r] + sm->P.p0.m[1][j][0][r];
                f2 = sm->P.p0.m[0][j][1][r] + sm->P.p0.m[1][j][1][r];
                g3 = sm->P.p0.m[0][j][2][r] + sm->P.p0.m[1][j][2][r];
            } else {
                int ju = j - 256;
                f1 = 0.f; f2 = 0.f; g3 = 0.f;
#pragma unroll
                for (int ch = 0; ch < T0_CH; ++ch) {
                    f1 += sm->P.p0.x[ch][ju][0][r];
                    f2 += sm->P.p0.x[ch][ju][1][r];
                    g3 += sm->P.p0.x[ch][ju][2][r];
                }
            }
            float n = cfc_cell(f1, f2, g3);
            sm->xt1[j][r] = n;
            sm->xt0[nb][DIN + j][r] = n;
        }
        __syncthreads();

        // ===== layer 1 gemm ===== units (j, ks in {0,1,2}), K = 150/150/148
        {
            int ks = tid / NH1;                // 0..2 (tid<512 -> ks=2 has j<154)
            int j = tid - ks * NH1;
            int klen = (ks < 2) ? 150 : 148;
            float a1[M], a2[M], a3[M];
            float bf1 = 0.f, bf2 = 0.f, bt = 0.f;
            if (ks == 0) { bf1 = sm->b1[j]; bf2 = sm->b1[NH1 + j]; bt = sm->b1[2 * NH1 + j]; }
#pragma unroll
            for (int r = 0; r < M; ++r) { a1[r] = bf1; a2[r] = bf2; a3[r] = bt; }
            gemm3_rt<NH1, GS1>(g_W1, j, ks * 150, klen, sm->xt1, a1, a2, a3);
            store_part(sm->P.p1.m[ks][j], a1, a2, a3);
        }
        // tail: ks=2, j=154..178, K=148 as 13 chunks (12x12 + 1x4) over 325 threads
        if (tid < 25 * T1_CH) {
            int jx = tid % 25, ch = tid / 25;  // ch 0..12
            int j = 154 + jx;
            int k0 = 300 + ch * T1_KL;
            int klen = (ch == T1_CH - 1) ? (148 - 12 * T1_KL) : T1_KL;  // 4 or 12
            float a1[M], a2[M], a3[M];
#pragma unroll
            for (int r = 0; r < M; ++r) { a1[r] = 0.f; a2[r] = 0.f; a3[r] = 0.f; }
            gemm3_rt<NH1, GS1>(g_W1, j, k0, klen, sm->xt1, a1, a2, a3);
            store_part(sm->P.p1.x[ch][jx], a1, a2, a3);
        }
        __syncthreads();

        // ===== layer 1 reduce + activate ===== 179*8 cells
        for (int c = tid; c < NH1 * M; c += BT) {
            int j = c >> 3, r = c & 7;
            float f1 = sm->P.p1.m[0][j][0][r] + sm->P.p1.m[1][j][0][r];
            float f2 = sm->P.p1.m[0][j][1][r] + sm->P.p1.m[1][j][1][r];
            float g3 = sm->P.p1.m[0][j][2][r] + sm->P.p1.m[1][j][2][r];
            if (j < 154) {
                f1 += sm->P.p1.m[2][j][0][r];
                f2 += sm->P.p1.m[2][j][1][r];
                g3 += sm->P.p1.m[2][j][2][r];
            } else {
                int jx = j - 154;
#pragma unroll
                for (int ch = 0; ch < T1_CH; ++ch) {
                    f1 += sm->P.p1.x[ch][jx][0][r];
                    f2 += sm->P.p1.x[ch][jx][1][r];
                    g3 += sm->P.p1.x[ch][jx][2][r];
                }
            }
            float n = cfc_cell(f1, f2, g3);
            sm->xt2[j][r] = n;
            sm->xt1[NH0 + j][r] = n;
        }
        __syncthreads();

        // ===== layer 2 gemm ===== units (j, kq in 0..7), K = 31x4 / 30x4
        {
            int kq = tid >> 6, j = tid & 63;
            float a1[M], a2[M], a3[M];
            float bf1 = 0.f, bf2 = 0.f, bt = 0.f;
            if (kq == 0) { bf1 = sm->b2[j]; bf2 = sm->b2[NH2 + j]; bt = sm->b2[2 * NH2 + j]; }
#pragma unroll
            for (int r = 0; r < M; ++r) { a1[r] = bf1; a2[r] = bf2; a3[r] = bt; }
            if (kq < 4)
                gemm3_t<31, NH2, GS2>(g_W2, j, kq * 31, sm->xt2, a1, a2, a3);
            else
                gemm3_t<30, NH2, GS2>(g_W2, j, 124 + (kq - 4) * 30, sm->xt2, a1, a2, a3);
            store_part(sm->P.p2[kq][j], a1, a2, a3);
        }
        __syncthreads();

        // ===== layer 2 reduce + activate ===== 64*8 = 512 cells, one per thread
        {
            int j = tid >> 3, r = tid & 7;
            float f1 = 0.f, f2 = 0.f, g3 = 0.f;
#pragma unroll
            for (int kq = 0; kq < 8; ++kq) {
                f1 += sm->P.p2[kq][j][0][r];
                f2 += sm->P.p2[kq][j][1][r];
                g3 += sm->P.p2[kq][j][2][r];
            }
            sm->xt2[NH1 + j][r] = cfc_cell(f1, f2, g3);
        }
        __syncthreads();

        // ===== fused output projection + x(t+1) store =====
        {
            int r = tid >> 6, o = tid & 63;
            float a = sm->fcb[o];
#pragma unroll 8
            for (int mm = 0; mm < OUTD; ++mm)
                a += sm->fcT[mm * OUTD + o] * sm->xt2[NH1 + mm][r];
            out[((long long)(row0 + r) * Tsz + t) * OUTD + o] = a;
        }
        if (t + 1 < Tsz) {
            sm->xt0[nb][xc][xr]      = rx0;
            sm->xt0[nb][xc + 64][xr] = rx1;
        }
        __syncthreads();
    }

    // ---- final hidden state (Tsz even -> final h0 in buffer 0) ----
    float* hn = out + PRED_ELEMS;
    for (int i = tid; i < M * 512; i += BT) {
        int r = i >> 9, c = i & 511;
        float v;
        if (c < NH0)            v = sm->xt0[0][DIN + c][r];
        else if (c < NH0 + NH1) v = sm->xt1[c][r];
        else                    v = sm->xt2[NH1 + (c - NH0 - NH1)][r];
        hn[(long long)(row0 + r) * 512 + c] = v;
    }
}

// ---------------- host launcher ----------------
extern "C" void kernel_launch(void* const* d_in, const int* in_sizes, int n_in,
                              void* d_out, int out_size) {
    (void)n_in; (void)out_size;
    const float* x      = (const float*)d_in[0];
    const float* hidden = (const float*)d_in[1];
    const void*  m0     = d_in[2];
    const void*  m1     = d_in[3];
    const void*  m2     = d_in[4];
    const float* ff1_w0 = (const float*)d_in[5];
    const float* ff1_b0 = (const float*)d_in[6];
    const float* ff2_w0 = (const float*)d_in[7];
    const float* ff2_b0 = (const float*)d_in[8];
    const float* ta_w0  = (const float*)d_in[9];
    const float* ta_b0  = (const float*)d_in[10];
    const float* tb_w0  = (const float*)d_in[11];
    const float* tb_b0  = (const float*)d_in[12];
    const float* ff1_w1 = (const float*)d_in[13];
    const float* ff1_b1 = (const float*)d_in[14];
    const float* ff2_w1 = (const float*)d_in[15];
    const float* ff2_b1 = (const float*)d_in[16];
    const float* ta_w1  = (const float*)d_in[17];
    const float* ta_b1  = (const float*)d_in[18];
    const float* tb_w1  = (const float*)d_in[19];
    const float* tb_b1  = (const float*)d_in[20];
    const float* ff1_w2 = (const float*)d_in[21];
    const float* ff1_b2 = (const float*)d_in[22];
    const float* ff2_w2 = (const float*)d_in[23];
    const float* ff2_b2 = (const float*)d_in[24];
    const float* ta_w2  = (const float*)d_in[25];
    const float* ta_b2  = (const float*)d_in[26];
    const float* tb_w2  = (const float*)d_in[27];
    const float* tb_b2  = (const float*)d_in[28];
    const float* fc_w   = (const float*)d_in[29];
    const float* fc_b   = (const float*)d_in[30];
    float* out = (float*)d_out;

    detect_kernel<<<3, 256>>>(m0, in_sizes[2], m1, in_sizes[3], m2, in_sizes[4]);

    prep_all<<<1024, 256>>>(
        ff1_w0, ff2_w0, ta_w0, tb_w0, ff1_b0, ff2_b0, ta_b0, tb_b0,
        ff1_w1, ff2_w1, ta_w1, tb_w1, ff1_b1, ff2_b1, ta_b1, tb_b1,
        ff1_w2, ff2_w2, ta_w2, tb_w2, ff1_b2, ff2_b2, ta_b2, tb_b2,
        m0, m1, m2);

    cudaFuncSetAttribute(ncp_main, cudaFuncAttributeMaxDynamicSharedMemorySize,
                         (int)sizeof(SM));
    ncp_main<<<Bsz / M, BT, sizeof(SM)>>>(x, hidden, fc_w, fc_b, out);
}